// round 1
// baseline (speedup 1.0000x reference)
#include <cuda_runtime.h>
#include <math.h>

#define BATCH 8192
#define D1    129
#define KPAD  132           // K padded to multiple of 4 (zeros contribute nothing)
#define BM    128
#define BN    128
#define BK    44            // 132 = 3 * 44
#define NKC   3

// Scratch (allocation-free: __device__ globals)
__device__ float g_AT[KPAD * BATCH];   // [k][i] = z1[i][k]
__device__ float g_BT[KPAD * BATCH];   // [k][j] = metric[k] * z2[j][k]
__device__ float g_rowsum[BATCH];
__device__ float g_colsum[BATCH];
__device__ float g_diag[BATCH];        // sims[i][i]

__global__ void prep_kernel(const float* __restrict__ z1, const float* __restrict__ z2) {
    int idx = blockIdx.x * 256 + threadIdx.x;
    if (idx >= KPAD * BATCH) return;
    int k = idx / BATCH;
    int i = idx % BATCH;
    float a = 0.f, b = 0.f;
    if (k < D1) {
        a = z1[i * D1 + k];
        b = z2[i * D1 + k];
        if (k == 0) b = -b;          // Lorentz metric
    }
    g_AT[idx] = a;
    g_BT[idx] = b;
}

__global__ void zero_kernel() {
    int i = blockIdx.x * 256 + threadIdx.x;
    if (i < BATCH) { g_rowsum[i] = 0.f; g_colsum[i] = 0.f; }
}

__global__ __launch_bounds__(256) void gemm_fused_kernel() {
    __shared__ float As[BK][BM];   // K-major: As[k][row]
    __shared__ float Bs[BK][BN];   // K-major: Bs[k][col]

    const int tx = threadIdx.x & 15;      // 16 threads across cols
    const int ty = threadIdx.x >> 4;      // 16 threads across rows
    const int r0 = blockIdx.y * BM;
    const int c0 = blockIdx.x * BN;

    float acc[8][8];
    #pragma unroll
    for (int i = 0; i < 8; ++i)
        #pragma unroll
        for (int j = 0; j < 8; ++j) acc[i][j] = 0.f;

    for (int kc = 0; kc < NKC; ++kc) {
        const int kbase = kc * BK;
        // Load tiles: warp covers one k-row of 32 float4s -> fully coalesced, conflict-free
        for (int idx = threadIdx.x; idx < BK * (BM / 4); idx += 256) {
            int kk = idx >> 5;            // idx / 32
            int c4 = idx & 31;            // idx % 32
            *(float4*)&As[kk][c4 * 4] = *(const float4*)&g_AT[(kbase + kk) * BATCH + r0 + c4 * 4];
            *(float4*)&Bs[kk][c4 * 4] = *(const float4*)&g_BT[(kbase + kk) * BATCH + c0 + c4 * 4];
        }
        __syncthreads();

        #pragma unroll 4
        for (int kk = 0; kk < BK; ++kk) {
            float a[8], b[8];
            *(float4*)&a[0] = *(float4*)&As[kk][ty * 8];
            *(float4*)&a[4] = *(float4*)&As[kk][ty * 8 + 4];
            *(float4*)&b[0] = *(float4*)&Bs[kk][tx * 8];
            *(float4*)&b[4] = *(float4*)&Bs[kk][tx * 8 + 4];
            #pragma unroll
            for (int i = 0; i < 8; ++i)
                #pragma unroll
                for (int j = 0; j < 8; ++j)
                    acc[i][j] = fmaf(a[i], b[j], acc[i][j]);
        }
        __syncthreads();
    }

    // Epilogue: e = exp(-acosh(max(-inner, 1+eps)) / TEMP); accumulate row/col sums
    float rsum[8], csum[8];
    #pragma unroll
    for (int i = 0; i < 8; ++i) { rsum[i] = 0.f; csum[i] = 0.f; }

    const bool diag_block = (r0 == c0);
    #pragma unroll
    for (int i = 0; i < 8; ++i) {
        #pragma unroll
        for (int j = 0; j < 8; ++j) {
            float t = fmaxf(-acc[i][j], 1.0f + 1e-6f);
            float d = acoshf(t);
            float s = -d / 0.07f;
            float e = expf(s);
            rsum[i] += e;
            csum[j] += e;
            if (diag_block && (ty * 8 + i) == (tx * 8 + j))
                g_diag[r0 + ty * 8 + i] = s;
        }
    }

    // Row reduction: sum across tx (16-lane halves of each warp)
    #pragma unroll
    for (int i = 0; i < 8; ++i) {
        float v = rsum[i];
        v += __shfl_xor_sync(0xffffffffu, v, 1);
        v += __shfl_xor_sync(0xffffffffu, v, 2);
        v += __shfl_xor_sync(0xffffffffu, v, 4);
        v += __shfl_xor_sync(0xffffffffu, v, 8);
        if (tx == 0) atomicAdd(&g_rowsum[r0 + ty * 8 + i], v);
    }

    // Column reduction: stage per-thread partials in smem (reuse As), sum across ty
    __syncthreads();
    float* cs = &As[0][0];                // needs 16*128 floats; As holds 44*128
    #pragma unroll
    for (int j = 0; j < 8; ++j)
        cs[ty * BN + tx * 8 + j] = csum[j];
    __syncthreads();
    if (threadIdx.x < BN) {
        float v = 0.f;
        #pragma unroll
        for (int t = 0; t < 16; ++t) v += cs[t * BN + threadIdx.x];
        atomicAdd(&g_colsum[c0 + threadIdx.x], v);
    }
}

__global__ void final_kernel(float* __restrict__ out) {
    __shared__ float red[256];
    float s = 0.f;
    for (int i = threadIdx.x; i < BATCH; i += 256) {
        // loss_i = (LSE_row + LSE_col)/2 - sims_ii   (no max-shift needed: sims <= -0.02)
        s += 0.5f * (logf(g_rowsum[i]) + logf(g_colsum[i])) - g_diag[i];
    }
    red[threadIdx.x] = s;
    __syncthreads();
    for (int stride = 128; stride > 0; stride >>= 1) {
        if (threadIdx.x < stride) red[threadIdx.x] += red[threadIdx.x + stride];
        __syncthreads();
    }
    if (threadIdx.x == 0) out[0] = red[0] * (1.0f / (float)BATCH);
}

extern "C" void kernel_launch(void* const* d_in, const int* in_sizes, int n_in,
                              void* d_out, int out_size) {
    const float* z1 = (const float*)d_in[0];
    const float* z2 = (const float*)d_in[1];
    float* out = (float*)d_out;

    zero_kernel<<<(BATCH + 255) / 256, 256>>>();
    prep_kernel<<<(KPAD * BATCH + 255) / 256, 256>>>(z1, z2);
    dim3 grid(BATCH / BN, BATCH / BM);   // (cols, rows) = (64, 64)
    gemm_fused_kernel<<<grid, 256>>>();
    final_kernel<<<1, 256>>>(out);
}